// round 5
// baseline (speedup 1.0000x reference)
#include <cuda_runtime.h>

// Problem constants (from reference)
#define CUBE_L   512
#define EQU_H    1024
#define EQU_W    2048
#define N_EQU    4
#define N_CH     3
#define N_PIX    (EQU_H * EQU_W)        // 2,097,152
#define LL       (CUBE_L * CUBE_L)      // 262,144
#define NPLANE   (N_EQU * N_CH)         // 12
#define HALF     (NPLANE / 2)           // 6 planes per batch

// 32x8 pixel tile per block. Planes processed in two batches of 6:
// 24 gather loads in flight per batch (good MLP) while
// __launch_bounds__(256,4) keeps regs <=48 so occupancy stays ~56%.
// Batch-1 stores interleave with batch-2 load issue.
__global__ __launch_bounds__(256, 4)
void cube2equirec_kernel(const float* __restrict__ x,
                         const float2* __restrict__ uv,
                         const int* __restrict__ face,
                         float* __restrict__ out)
{
    const int px = blockIdx.x * 32 + threadIdx.x;   // 0..2047
    const int py = blockIdx.y * 8  + threadIdx.y;   // 0..1023
    const int p  = py * EQU_W + px;

    const float2 t = uv[p];
    const float u = t.x, v = t.y;
    const int f = face[p];

    int x0 = (int)floorf(u);
    int y0 = (int)floorf(v);
    x0 = min(max(x0, 0), CUBE_L - 1);
    y0 = min(max(y0, 0), CUBE_L - 1);
    const int x1 = min(x0 + 1, CUBE_L - 1);
    const int y1 = min(y0 + 1, CUBE_L - 1);
    const float wx = u - (float)x0;
    const float wy = v - (float)y0;

    const float w00 = (1.0f - wx) * (1.0f - wy);
    const float w01 = wx * (1.0f - wy);
    const float w10 = (1.0f - wx) * wy;
    const float w11 = wx * wy;

    const int o00 = y0 * CUBE_L + x0;
    const int o01 = y0 * CUBE_L + x1;
    const int o10 = y1 * CUBE_L + x0;
    const int o11 = y1 * CUBE_L + x1;

    const float* xf = x + f * (N_CH * LL);

    // Plane i = e*3 + c ; element offset = e*(18*LL) + c*LL
    #pragma unroll
    for (int half = 0; half < 2; half++) {
        const int pb = half * HALF;   // first plane of this batch

        float g00[HALF], g01[HALF], g10[HALF], g11[HALF];
        #pragma unroll
        for (int j = 0; j < HALF; j++) {
            const int i = pb + j;
            const int e = i / N_CH;
            const int c = i % N_CH;
            const float* xc = xf + e * (6 * N_CH * LL) + c * LL;
            g00[j] = __ldg(xc + o00);
            g01[j] = __ldg(xc + o01);
            g10[j] = __ldg(xc + o10);
            g11[j] = __ldg(xc + o11);
        }

        #pragma unroll
        for (int j = 0; j < HALF; j++) {
            float r = g00[j] * w00 + g01[j] * w01 + g10[j] * w10 + g11[j] * w11;
            __stcs(out + (size_t)(pb + j) * N_PIX + p, r);
        }
    }
}

extern "C" void kernel_launch(void* const* d_in, const int* in_sizes, int n_in,
                              void* d_out, int out_size)
{
    const float*  x    = (const float*)d_in[0];
    const float2* uv   = (const float2*)d_in[1];
    const int*    face = (const int*)d_in[2];
    float*        out  = (float*)d_out;

    dim3 block(32, 8);
    dim3 grid(EQU_W / 32, EQU_H / 8);
    cube2equirec_kernel<<<grid, block>>>(x, uv, face, out);
}

// round 7
// speedup vs baseline: 1.0050x; 1.0050x over previous
#include <cuda_runtime.h>
#include <cuda_fp16.h>

// Problem constants
#define CUBE_L   512
#define EQU_H    1024
#define EQU_W    2048
#define N_EQU    4
#define N_CH     3
#define N_PIX    (EQU_H * EQU_W)        // 2,097,152
#define LL       (CUBE_L * CUBE_L)      // 262,144
#define N_PLANES (N_CH * 6)             // 18 packed planes (c,f)

// Scratch: x repacked as x̃[(c*6+f)][y*L+x] = uint2 holding fp16 values for
// e = 0..3 (half2(e0,e1), half2(e2,e3)). 18 * 262144 * 8B = 37.75 MB.
__device__ uint2 g_xt[N_PLANES * LL];

static __device__ __forceinline__ unsigned int h2_as_u32(__half2 h) {
    return *reinterpret_cast<unsigned int*>(&h);
}
static __device__ __forceinline__ __half2 u32_as_h2(unsigned int u) {
    return *reinterpret_cast<__half2*>(&u);
}

// ---------------- Pass 1: repack x (fp32 [e][f][c][y][x]) -> fp16 e-packed ----
__global__ __launch_bounds__(256)
void repack_kernel(const float* __restrict__ x)
{
    int T = blockIdx.x * blockDim.x + threadIdx.x;   // 0 .. 18*LL-1
    int plane = T >> 18;          // T / LL   (c*6+f)
    int i     = T & (LL - 1);     // T % LL
    int c = plane / 6;
    int f = plane % 6;

    // in index for image e: (e*6 + f)*3*LL + c*LL + i
    int base = f * (N_CH * LL) + c * LL + i;
    float e0 = __ldg(x + base);
    float e1 = __ldg(x + base + 1 * 6 * N_CH * LL);
    float e2 = __ldg(x + base + 2 * 6 * N_CH * LL);
    float e3 = __ldg(x + base + 3 * 6 * N_CH * LL);

    uint2 v;
    v.x = h2_as_u32(__floats2half2_rn(e0, e1));
    v.y = h2_as_u32(__floats2half2_rn(e2, e3));
    g_xt[T] = v;
}

// ---------------- Pass 2: gather + bilinear from packed taps ------------------
// 32x8 pixel tile per block. Per pixel: 12 LDG.64 gathers (4 taps x 3 channels,
// each load carrying all 4 equirect images) + 12 fp32 stores.
__global__ __launch_bounds__(256)
void cube2equirec_kernel(const float2* __restrict__ uv,
                         const int* __restrict__ face,
                         float* __restrict__ out)
{
    const int px = blockIdx.x * 32 + threadIdx.x;
    const int py = blockIdx.y * 8  + threadIdx.y;
    const int p  = py * EQU_W + px;

    const float2 t = uv[p];
    const float u = t.x, v = t.y;
    const int f = face[p];

    int x0 = (int)floorf(u);
    int y0 = (int)floorf(v);
    x0 = min(max(x0, 0), CUBE_L - 1);
    y0 = min(max(y0, 0), CUBE_L - 1);
    const int x1 = min(x0 + 1, CUBE_L - 1);
    const int y1 = min(y0 + 1, CUBE_L - 1);
    const float wx = u - (float)x0;
    const float wy = v - (float)y0;

    const float w00 = (1.0f - wx) * (1.0f - wy);
    const float w01 = wx * (1.0f - wy);
    const float w10 = (1.0f - wx) * wy;
    const float w11 = wx * wy;

    const int o00 = y0 * CUBE_L + x0;
    const int o01 = y0 * CUBE_L + x1;
    const int o10 = y1 * CUBE_L + x0;
    const int o11 = y1 * CUBE_L + x1;

    // Issue all 12 gathers up front (MLP).
    uint2 g[N_CH][4];
    #pragma unroll
    for (int c = 0; c < N_CH; c++) {
        const uint2* b = g_xt + (c * 6 + f) * LL;
        g[c][0] = __ldg(b + o00);
        g[c][1] = __ldg(b + o01);
        g[c][2] = __ldg(b + o10);
        g[c][3] = __ldg(b + o11);
    }

    const float w[4] = {w00, w01, w10, w11};

    #pragma unroll
    for (int c = 0; c < N_CH; c++) {
        float r01x = 0.f, r01y = 0.f, r23x = 0.f, r23y = 0.f;
        #pragma unroll
        for (int tap = 0; tap < 4; tap++) {
            float2 a01 = __half22float2(u32_as_h2(g[c][tap].x)); // e0,e1
            float2 a23 = __half22float2(u32_as_h2(g[c][tap].y)); // e2,e3
            r01x += w[tap] * a01.x;
            r01y += w[tap] * a01.y;
            r23x += w[tap] * a23.x;
            r23y += w[tap] * a23.y;
        }
        __stcs(out + (size_t)(0 * N_CH + c) * N_PIX + p, r01x);
        __stcs(out + (size_t)(1 * N_CH + c) * N_PIX + p, r01y);
        __stcs(out + (size_t)(2 * N_CH + c) * N_PIX + p, r23x);
        __stcs(out + (size_t)(3 * N_CH + c) * N_PIX + p, r23y);
    }
}

extern "C" void kernel_launch(void* const* d_in, const int* in_sizes, int n_in,
                              void* d_out, int out_size)
{
    const float*  x    = (const float*)d_in[0];
    const float2* uv   = (const float2*)d_in[1];
    const int*    face = (const int*)d_in[2];
    float*        out  = (float*)d_out;

    // Pass 1: repack (18*LL threads)
    repack_kernel<<<(N_PLANES * LL) / 256, 256>>>(x);

    // Pass 2: gather
    dim3 block(32, 8);
    dim3 grid(EQU_W / 32, EQU_H / 8);
    cube2equirec_kernel<<<grid, block>>>(uv, face, out);
}